// round 1
// baseline (speedup 1.0000x reference)
#include <cuda_runtime.h>
#include <math.h>

// Problem constants
#define NB 32
#define NA 5
#define NCH 160          // NA * (19 + 13)
#define NHW 76
#define HW (NHW * NHW)   // 5776
#define NT 50
#define TSTRIDE 21
#define IMW 640.0f
#define IMH 480.0f
#define TH 80.0f
#define SHARP 2.0f

__device__ double g_acc;

__device__ __forceinline__ float sigmoidf_(float x) {
    return 1.0f / (1.0f + expf(-x));
}

__global__ void k_zero() { g_acc = 0.0; }

// Background conf term: 0.5 * sum over (b, a, h, w) of sigmoid(out[b, a*32+18, h, w])^2
__global__ void k_conf(const float* __restrict__ O) {
    const int N = NB * NA * HW;
    float local = 0.0f;
    for (int idx = blockIdx.x * blockDim.x + threadIdx.x; idx < N;
         idx += gridDim.x * blockDim.x) {
        int p = idx % HW;
        int r = idx / HW;
        int a = r % NA;
        int b = r / NA;
        float v = O[(size_t)b * NCH * HW + (size_t)(a * 32 + 18) * HW + p];
        float s = sigmoidf_(v);
        local += s * s;
    }
    // warp reduce
    for (int off = 16; off > 0; off >>= 1)
        local += __shfl_down_sync(0xFFFFFFFFu, local, off);
    __shared__ float warp_sums[32];
    int lane = threadIdx.x & 31, wid = threadIdx.x >> 5;
    if (lane == 0) warp_sums[wid] = local;
    __syncthreads();
    if (wid == 0) {
        float s = (lane < (blockDim.x >> 5)) ? warp_sums[lane] : 0.0f;
        for (int off = 16; off > 0; off >>= 1)
            s += __shfl_down_sync(0xFFFFFFFFu, s, off);
        if (lane == 0) atomicAdd(&g_acc, 0.5 * (double)s);
    }
}

// Per-target terms. One block per batch; last-write-wins scatter semantics.
__global__ void k_targets(const float* __restrict__ O, const float* __restrict__ T) {
    int b = blockIdx.x;
    int t = threadIdx.x;
    __shared__ int s_gi[NT], s_gj[NT], s_nz[NT], s_valid[NT];

    if (t < NT) {
        float c0 = T[b * (NT * TSTRIDE) + t * TSTRIDE + 1];
        float c1 = T[b * (NT * TSTRIDE) + t * TSTRIDE + 2];
        s_gi[t] = (int)floorf(c0 * (float)NHW);
        s_gj[t] = (int)floorf(c1 * (float)NHW);
        s_nz[t] = (c0 != 0.0f) ? 1 : 0;
    }
    __syncthreads();
    if (t == 0) {
        int v = 1;
        for (int i = 0; i < NT; i++) { v &= s_nz[i]; s_valid[i] = v; }
    }
    __syncthreads();

    if (t >= NT || !s_valid[t]) return;
    int gi = s_gi[t], gj = s_gj[t];
    // OOB scatter indices are dropped by XLA -> this target never lands
    if (gi < 0 || gi >= NHW || gj < 0 || gj >= NHW) return;

    // last-write-wins: skip if a later valid target maps to the same cell
    for (int t2 = t + 1; t2 < NT && s_valid[t2]; t2++) {
        if (s_gi[t2] == gi && s_gj[t2] == gj) return;
    }

    // load 18 coords for this target
    float coords[18];
    const float* tp = T + b * (NT * TSTRIDE) + t * TSTRIDE + 1;
#pragma unroll
    for (int c = 0; c < 18; c++) coords[c] = tp[c];

    // predictions at anchor 0, cell (gj, gi): channels 0..18 of batch b
    const float* base = O + (size_t)b * NCH * HW + (size_t)gj * NHW + gi;
    float raw[19];
#pragma unroll
    for (int c = 0; c < 19; c++) raw[c] = base[(size_t)c * HW];

    // loss_xy contribution
    float lxy = 0.0f;
#pragma unroll
    for (int c = 0; c < 18; c++) {
        float pred = (c < 2) ? sigmoidf_(raw[c]) : raw[c];
        float g = (c & 1) ? (float)gj : (float)gi;
        float tv = coords[c] * (float)NHW - g;
        float d = pred - tv;
        lxy += d * d;
    }

    // conf_t: corner-distance score from stop-gradient predictions
    float csum = 0.0f;
#pragma unroll
    for (int k = 0; k < 9; k++) {
        float xp = (k == 0) ? sigmoidf_(raw[0]) : raw[2 * k];
        float yp = (k == 0) ? sigmoidf_(raw[1]) : raw[2 * k + 1];
        float px = (xp + (float)gi) / (float)NHW;
        float py = (yp + (float)gj) / (float)NHW;
        float dx = (coords[2 * k]     - px) * IMW;
        float dy = (coords[2 * k + 1] - py) * IMH;
        float dn = sqrtf(dx * dx + dy * dy);
        float cv = (dn < TH) ? (expf(SHARP * (1.0f - dn / TH)) - 1.0f) : 0.0f;
        csum += cv;
    }
    float conf_t = (csum / 9.0f) / (expf(SHARP) - 1.0f + 1e-05f);

    float conf = sigmoidf_(raw[18]);
    // replace the generic conf^2 term (already counted in k_conf) with obj term
    float dc = conf - conf_t;
    float term = 0.5f * (5.0f * dc * dc - conf * conf) + 0.5f * lxy;

    atomicAdd(&g_acc, (double)term);
}

__global__ void k_final(float* out) { out[0] = (float)g_acc; }

extern "C" void kernel_launch(void* const* d_in, const int* in_sizes, int n_in,
                              void* d_out, int out_size) {
    const float* O = (const float*)d_in[0];
    const float* T = (const float*)d_in[1];
    float* out = (float*)d_out;
    (void)in_sizes; (void)n_in; (void)out_size;

    k_zero<<<1, 1>>>();
    k_conf<<<512, 256>>>(O);
    k_targets<<<NB, 64>>>(O, T);
    k_final<<<1, 1>>>(out);
}